// round 1
// baseline (speedup 1.0000x reference)
#include <cuda_runtime.h>
#include <cstddef>

// Feature_Embedding (FFM-style pairwise field interactions)
// x: (B=4096, F=16) int32 indices into vocab V=100000
// W: (F=16, V=100000, D=64) fp32
// out: (B, 120*64 + 16*64) = (B, 8704) fp32
//   out[b, p*64+d]        = W[j_p, x[b,i_p], d] * W[i_p, x[b,j_p], d]   (p over triu pairs i<j)
//   out[b, 7680 + f*64+d] = W[f, x[b,f], d]
//
// Each gathered embedding vector is consumed exactly once -> direct
// gather/multiply/store, fully memory-bound (~405 MB traffic).

constexpr int F_FIELDS = 16;
constexpr int D_LAT    = 64;
constexpr int V_VOCAB  = 100000;
constexpr int N_PAIRS  = 120;           // 16*15/2
constexpr int N_UNITS  = N_PAIRS + F_FIELDS;   // 136
constexpr int OUT_COLS = N_UNITS * D_LAT;      // 8704
constexpr int ROW_F4   = D_LAT / 4;            // 16 float4 per embedding row

__global__ __launch_bounds__(256, 8)
void ffm_interact_kernel(const int* __restrict__ x,
                         const float* __restrict__ W,
                         float* __restrict__ out)
{
    __shared__ int sx[F_FIELDS];
    __shared__ unsigned char si[N_PAIRS];
    __shared__ unsigned char sj[N_PAIRS];

    const int tid = threadIdx.x;
    const int b   = blockIdx.x;

    if (tid < F_FIELDS) {
        sx[tid] = x[b * F_FIELDS + tid];
    }
    if (tid < N_PAIRS) {
        // invert triu(k=1) flat index -> (i, j)
        int rem = tid;
        int i = 0;
        while (rem >= (F_FIELDS - 1) - i) {
            rem -= (F_FIELDS - 1) - i;
            ++i;
        }
        si[tid] = (unsigned char)i;
        sj[tid] = (unsigned char)(i + 1 + rem);
    }
    __syncthreads();

    const float4* __restrict__ W4 = reinterpret_cast<const float4*>(W);
    float4* __restrict__ out4 =
        reinterpret_cast<float4*>(out) + (size_t)b * (OUT_COLS / 4);

    const int lane = tid & (ROW_F4 - 1);   // float4 lane within 64-dim row
    const int w    = tid >> 4;             // unit stripe base (0..15)

    #pragma unroll
    for (int it = 0; it < 9; ++it) {
        const int u = w + it * 16;
        if (u >= N_UNITS) break;
        if (u < N_PAIRS) {
            const int i = si[u];
            const int j = sj[u];
            const size_t offA = ((size_t)j * V_VOCAB + (size_t)sx[i]) * ROW_F4 + lane;
            const size_t offB = ((size_t)i * V_VOCAB + (size_t)sx[j]) * ROW_F4 + lane;
            const float4 a  = __ldg(&W4[offA]);
            const float4 bb = __ldg(&W4[offB]);
            float4 r;
            r.x = a.x * bb.x;
            r.y = a.y * bb.y;
            r.z = a.z * bb.z;
            r.w = a.w * bb.w;
            out4[(size_t)u * ROW_F4 + lane] = r;
        } else {
            const int f = u - N_PAIRS;
            const size_t off = ((size_t)f * V_VOCAB + (size_t)sx[f]) * ROW_F4 + lane;
            out4[(size_t)u * ROW_F4 + lane] = __ldg(&W4[off]);
        }
    }
}

extern "C" void kernel_launch(void* const* d_in, const int* in_sizes, int n_in,
                              void* d_out, int out_size)
{
    const int*   x = (const int*)d_in[0];
    const float* W = (const float*)d_in[1];
    float*       o = (float*)d_out;

    const int B = in_sizes[0] / F_FIELDS;   // 4096

    ffm_interact_kernel<<<B, 256>>>(x, W, o);
}

// round 2
// speedup vs baseline: 1.0253x; 1.0253x over previous
#include <cuda_runtime.h>
#include <cstddef>

// Feature_Embedding (FFM-style pairwise field interactions)
// x: (B=4096, F=16) int32 indices, W: (16, 100000, 64) fp32
// out: (B, 8704):  120 pair products (triu k=1) then 16 diag embeddings.
// Pure gather->mul->store, HBM-bound (~411 MB). Barrier-free version:
// pair table in __constant__, x broadcast via shfl, streaming stores.

constexpr int F_FIELDS = 16;
constexpr int V_VOCAB  = 100000;
constexpr int N_PAIRS  = 120;
constexpr int N_UNITS  = 136;            // 120 pairs + 16 diag
constexpr int OUT_F4   = N_UNITS * 16;   // 2176 float4 per row
constexpr int ROW_F4   = 16;             // 64 floats = 16 float4

// pair_tab[u] = i | (j<<8) for u<120 (triu k=1 row-major); u>=120 -> diag field u-120
__constant__ unsigned short c_pair[N_UNITS] = {
    // i=0
    0x0100,0x0200,0x0300,0x0400,0x0500,0x0600,0x0700,0x0800,
    0x0900,0x0A00,0x0B00,0x0C00,0x0D00,0x0E00,0x0F00,
    // i=1
    0x0201,0x0301,0x0401,0x0501,0x0601,0x0701,0x0801,0x0901,
    0x0A01,0x0B01,0x0C01,0x0D01,0x0E01,0x0F01,
    // i=2
    0x0302,0x0402,0x0502,0x0602,0x0702,0x0802,0x0902,0x0A02,
    0x0B02,0x0C02,0x0D02,0x0E02,0x0F02,
    // i=3
    0x0403,0x0503,0x0603,0x0703,0x0803,0x0903,0x0A03,0x0B03,
    0x0C03,0x0D03,0x0E03,0x0F03,
    // i=4
    0x0504,0x0604,0x0704,0x0804,0x0904,0x0A04,0x0B04,0x0C04,
    0x0D04,0x0E04,0x0F04,
    // i=5
    0x0605,0x0705,0x0805,0x0905,0x0A05,0x0B05,0x0C05,0x0D05,
    0x0E05,0x0F05,
    // i=6
    0x0706,0x0806,0x0906,0x0A06,0x0B06,0x0C06,0x0D06,0x0E06,0x0F06,
    // i=7
    0x0807,0x0907,0x0A07,0x0B07,0x0C07,0x0D07,0x0E07,0x0F07,
    // i=8
    0x0908,0x0A08,0x0B08,0x0C08,0x0D08,0x0E08,0x0F08,
    // i=9
    0x0A09,0x0B09,0x0C09,0x0D09,0x0E09,0x0F09,
    // i=10
    0x0B0A,0x0C0A,0x0D0A,0x0E0A,0x0F0A,
    // i=11
    0x0C0B,0x0D0B,0x0E0B,0x0F0B,
    // i=12
    0x0D0C,0x0E0C,0x0F0C,
    // i=13
    0x0E0D,0x0F0D,
    // i=14
    0x0F0E,
    // diag f = u-120 (encode i=j=f)
    0x0000,0x0101,0x0202,0x0303,0x0404,0x0505,0x0606,0x0707,
    0x0808,0x0909,0x0A0A,0x0B0B,0x0C0C,0x0D0D,0x0E0E,0x0F0F
};

__global__ __launch_bounds__(256, 8)
void ffm_interact_kernel(const int* __restrict__ x,
                         const float* __restrict__ W,
                         float* __restrict__ out)
{
    const int tid  = threadIdx.x;
    const int b    = blockIdx.x;
    const int lane = tid & (ROW_F4 - 1);   // float4 lane within 64-dim row
    const int w    = tid >> 4;             // unit stripe base (0..15)
    const int lid  = tid & 31;

    // each warp loads the 16-field index row; broadcast via shuffle
    const int myx = __ldg(&x[b * F_FIELDS + (lid & 15)]);

    const float4* __restrict__ W4 = reinterpret_cast<const float4*>(W);
    float4* __restrict__ out4 =
        reinterpret_cast<float4*>(out) + (size_t)b * OUT_F4;

    #pragma unroll
    for (int it = 0; it < 9; ++it) {
        const int u = w + it * 16;
        if (u < N_PAIRS) {
            const unsigned int pt = c_pair[u];
            const int i = (int)(pt & 0xFF);
            const int j = (int)(pt >> 8);
            const int xi = __shfl_sync(0xFFFFFFFFu, myx, i);
            const int xj = __shfl_sync(0xFFFFFFFFu, myx, j);
            const size_t offA = ((size_t)j * V_VOCAB + (size_t)xi) * ROW_F4 + lane;
            const size_t offB = ((size_t)i * V_VOCAB + (size_t)xj) * ROW_F4 + lane;
            const float4 a  = __ldg(&W4[offA]);
            const float4 bb = __ldg(&W4[offB]);
            float4 r;
            r.x = a.x * bb.x;
            r.y = a.y * bb.y;
            r.z = a.z * bb.z;
            r.w = a.w * bb.w;
            __stcs(&out4[(size_t)u * ROW_F4 + lane], r);
        } else if (u < N_UNITS) {
            const int f = u - N_PAIRS;
            const int xf = __shfl_sync(0xFFFFFFFFu, myx, f);
            const size_t off = ((size_t)f * V_VOCAB + (size_t)xf) * ROW_F4 + lane;
            const float4 v = __ldg(&W4[off]);
            __stcs(&out4[(size_t)u * ROW_F4 + lane], v);
        }
    }
}

extern "C" void kernel_launch(void* const* d_in, const int* in_sizes, int n_in,
                              void* d_out, int out_size)
{
    const int*   x = (const int*)d_in[0];
    const float* W = (const float*)d_in[1];
    float*       o = (float*)d_out;

    const int B = in_sizes[0] / F_FIELDS;   // 4096

    ffm_interact_kernel<<<B, 256>>>(x, W, o);
}